// round 12
// baseline (speedup 1.0000x reference)
#include <cuda_runtime.h>
#include <cuda_fp16.h>
#include <cstdint>

#define HW 65536
#define M_PER_CH (16*HW)

__device__ __half g_convh[(size_t)16*64*HW];   // 128 MB fp16 scratch
__device__ float g_psum[64*148];
__device__ float g_psq[64*148];
__device__ float g_scale[64];
__device__ float g_shift[64];

// SMEM layout (dynamic), XOR-swizzled 128B rows (chunk o of row r at o^(r&7)):
//   W : [0, 73728)             9 taps x [64 co][64 ci] fp16
//   A : [73728, +8*16896)      8-slot ring x [132 px][64 ci] fp16
#define WSZ   73728
#define ATILE 16896
#define SMEM_REQ (73728 + 8*16896)

__device__ __forceinline__ uint32_t s2u(const void* p) {
    uint32_t a;
    asm("{ .reg .u64 t; cvta.to.shared.u64 t, %1; cvt.u32.u64 %0, t; }" : "=r"(a) : "l"(p));
    return a;
}
__device__ __forceinline__ void ldsm4(uint32_t& r0, uint32_t& r1, uint32_t& r2, uint32_t& r3,
                                      uint32_t addr) {
    asm volatile("ldmatrix.sync.aligned.m8n8.x4.shared.b16 {%0,%1,%2,%3}, [%4];"
                 : "=r"(r0), "=r"(r1), "=r"(r2), "=r"(r3) : "r"(addr));
}
__device__ __forceinline__ void mma16816(float* c, uint32_t a0, uint32_t a1, uint32_t a2,
                                         uint32_t a3, uint32_t b0, uint32_t b1) {
    asm volatile("mma.sync.aligned.m16n8k16.row.col.f32.f16.f16.f32 "
                 "{%0,%1,%2,%3}, {%4,%5,%6,%7}, {%8,%9}, {%0,%1,%2,%3};"
                 : "+f"(c[0]), "+f"(c[1]), "+f"(c[2]), "+f"(c[3])
                 : "r"(a0), "r"(a1), "r"(a2), "r"(a3), "r"(b0), "r"(b1));
}
__device__ __forceinline__ uint32_t packh2(float a, float b) {
    __half2 h = __floats2half2_rn(a, b);
    return *(uint32_t*)&h;
}

// Load one x row (132 px x 64 ci) into regs
__device__ __forceinline__ void stage_load(const float* __restrict__ x, int n, int hrow,
                                           int w0, int t, uint4 pk[4], uint4& pke)
{
    const bool rowok = ((unsigned)hrow < 256u);
    const int px   = t & 127;
    const int octh = t >> 7;
    const int wg   = w0 - 2 + px;
    const bool wok = rowok && ((unsigned)wg < 256u);
    const size_t rb = (size_t)(hrow*256 + wg);

    #pragma unroll
    for (int r = 0; r < 4; r++) {
        const int oct = 2*r + octh;
        const size_t base = (((size_t)(n*64 + oct*8)) << 16) + rb;
        float v[8];
        #pragma unroll
        for (int i = 0; i < 8; i++)
            v[i] = wok ? __ldg(&x[base + ((size_t)i << 16)]) : 0.f;
        pk[r].x = packh2(v[0], v[1]);
        pk[r].y = packh2(v[2], v[3]);
        pk[r].z = packh2(v[4], v[5]);
        pk[r].w = packh2(v[6], v[7]);
    }
    pke = make_uint4(0, 0, 0, 0);
    if (t < 32) {
        const int pxe = 128 + (t & 3);
        const int oct = t >> 2;
        const int we = w0 - 2 + pxe;
        const bool ewok = rowok && ((unsigned)we < 256u);
        const size_t base = (((size_t)(n*64 + oct*8)) << 16) + (size_t)(hrow*256 + we);
        float v[8];
        #pragma unroll
        for (int i = 0; i < 8; i++)
            v[i] = ewok ? __ldg(&x[base + ((size_t)i << 16)]) : 0.f;
        pke.x = packh2(v[0], v[1]);
        pke.y = packh2(v[2], v[3]);
        pke.z = packh2(v[4], v[5]);
        pke.w = packh2(v[6], v[7]);
    }
}

// Swizzled store of one staged row into ring slot
__device__ __forceinline__ void stage_store(char* sm, int slot, int t,
                                            const uint4 pk[4], const uint4& pke)
{
    char* base = sm + WSZ + slot * ATILE;
    const int px = t & 127, octh = t >> 7;
    const int pm = px & 7;
    #pragma unroll
    for (int r = 0; r < 4; r++) {
        const int oct = 2*r + octh;
        *(uint4*)(base + px*128 + ((oct ^ pm) << 4)) = pk[r];
    }
    if (t < 32) {
        const int pxe = 128 + (t & 3), oct = t >> 2;
        *(uint4*)(base + pxe*128 + ((oct ^ (pxe & 7)) << 4)) = pke;
    }
}

// ---------------------------------------------------------------------------
// HMMA implicit-GEMM dilated conv + fused channel stats.
// 256 threads / 8 warps: double-row iterations, warp = (row, M-pos), each
// warp M=32 x N=64. 8-slot swizzled A ring -> ONE sync per iteration.
// Output stored fp16 to g_convh; per-channel stats kept fp32 in registers.
// ---------------------------------------------------------------------------
__global__ __launch_bounds__(256, 1)
void conv_tc(const float* __restrict__ x, const float* __restrict__ wgt)
{
    extern __shared__ char sm[];
    __shared__ float sredS[8*64], sredQ[8*64];

    const int t  = threadIdx.x;
    const int L  = t & 31;
    const int wi = t >> 5;
    const int rsel = wi >> 2;            // 0: row h, 1: row h+2
    const int Pm   = (wi & 3) * 32;

    // ---- stage weights: [tap][co][ci] fp16, swizzled 128B rows ----
    {
        const int co = t & 63;
        const int o0 = t >> 6;   // 0..3
        const int cm = co & 7;
        for (int r = 0; r < 2; r++) {
            const int oct = o0 + 4*r;
            for (int tap = 0; tap < 9; tap++) {
                float v[8];
                #pragma unroll
                for (int i = 0; i < 8; i++)
                    v[i] = __ldg(&wgt[co*576 + (oct*8 + i)*9 + tap]);
                uint4 p;
                p.x = packh2(v[0], v[1]); p.y = packh2(v[2], v[3]);
                p.z = packh2(v[4], v[5]); p.w = packh2(v[6], v[7]);
                *(uint4*)(sm + tap*8192 + co*128 + ((oct ^ cm) << 4)) = p;
            }
        }
    }

    const uint32_t Wb = s2u(sm);
    const uint32_t Ab = Wb + WSZ;

    // B lane constants: co row and xor mask (<<4)
    const uint32_t bbase0 = Wb + (uint32_t)(((((L >> 3) & 3)*8) + (L & 7)) * 128);
    const uint32_t bbase1 = bbase0 + 32*128;
    const uint32_t bm4 = (uint32_t)((L & 7) << 4);

    // A lane constants per (mi, kw): row-byte base and (pxmask^hi)<<4
    const uint32_t h4 = (uint32_t)((L >> 4) << 4);
    uint32_t pa[2][3], hp4[2][3];
    #pragma unroll
    for (int mi = 0; mi < 2; mi++)
        #pragma unroll
        for (int kw = 0; kw < 3; kw++) {
            const int px = Pm + mi*16 + (L & 15) + 2*kw;
            pa[mi][kw]  = (uint32_t)(px * 128);
            hp4[mi][kw] = ((uint32_t)((px & 7) << 4)) ^ h4;
        }

    float2 accS2[8], accQ2[8];
    #pragma unroll
    for (int i = 0; i < 8; i++) {
        accS2[i] = make_float2(0.f, 0.f);
        accQ2[i] = make_float2(0.f, 0.f);
    }

    // double-tile partition: 4096 units over 148 CTAs; chain = 64 units
    const int d0 = (blockIdx.x * 4096) / 148;
    const int d1 = ((blockIdx.x + 1) * 4096) / 148;

    uint4 pkA[4], pkeA, pkB[4], pkeB;
    int D = d0;

    __syncthreads();   // weights staged

    while (D < d1) {
        const int chain = D >> 6;
        int k = D & 63;
        const int n  = chain >> 2;
        const int wc = (chain >> 1) & 1;
        const int p  = chain & 1;
        const int w0 = wc << 7;
        const int seg_end = (((chain + 1) << 6) < d1) ? ((chain + 1) << 6) : d1;

        __syncthreads();   // previous chain's ldsm reads done before slot reuse

        // prologue: slot j holds x-row p+2j-2
        stage_load(x, n, p + 4*k - 2, w0, t, pkA, pkeA);
        stage_store(sm, (2*k) & 7, t, pkA, pkeA);
        stage_load(x, n, p + 4*k, w0, t, pkA, pkeA);
        stage_store(sm, (2*k + 1) & 7, t, pkA, pkeA);
        stage_load(x, n, p + 4*k + 2, w0, t, pkA, pkeA);
        stage_load(x, n, p + 4*k + 4, w0, t, pkB, pkeB);

        for (; D < seg_end; D++, k++) {
            stage_store(sm, (2*k + 2) & 7, t, pkA, pkeA);
            stage_store(sm, (2*k + 3) & 7, t, pkB, pkeB);
            __syncthreads();   // the only per-iteration barrier

            // prefetch next 2 rows (hidden under the MMA loop)
            if (D + 1 < seg_end) {
                stage_load(x, n, p + 4*k + 6, w0, t, pkA, pkeA);
                stage_load(x, n, p + 4*k + 8, w0, t, pkB, pkeB);
            }

            float c[64];
            #pragma unroll
            for (int i = 0; i < 64; i++) c[i] = 0.f;

            #pragma unroll
            for (int kh = 0; kh < 3; kh++) {
                const int sl = (2*k + rsel + kh) & 7;
                const uint32_t abase = Ab + (uint32_t)sl * ATILE;
                #pragma unroll
                for (int kw = 0; kw < 3; kw++) {
                    const uint32_t a0b = abase + pa[0][kw];
                    const uint32_t a1b = abase + pa[1][kw];
                    const uint32_t x0 = hp4[0][kw];
                    const uint32_t x1 = hp4[1][kw];
                    const uint32_t bt0 = bbase0 + (uint32_t)((kh*3 + kw)*8192);
                    const uint32_t bt1 = bbase1 + (uint32_t)((kh*3 + kw)*8192);
                    #pragma unroll
                    for (int ks = 0; ks < 4; ks++) {
                        const uint32_t kc = (uint32_t)(2*ks) << 4;   // chunk 2ks
                        uint32_t A0[4], A1[4], B0[8], B1[8];
                        ldsm4(A0[0], A0[1], A0[2], A0[3], a0b + (kc ^ x0));
                        ldsm4(A1[0], A1[1], A1[2], A1[3], a1b + (kc ^ x1));
                        ldsm4(B0[0], B0[1], B0[2], B0[3], bt0 + (kc ^ bm4));
                        ldsm4(B1[0], B1[1], B1[2], B1[3], bt0 + ((kc + 16) ^ bm4));
                        ldsm4(B0[4], B0[5], B0[6], B0[7], bt1 + (kc ^ bm4));
                        ldsm4(B1[4], B1[5], B1[6], B1[7], bt1 + ((kc + 16) ^ bm4));
                        #pragma unroll
                        for (int nj = 0; nj < 8; nj++) {
                            mma16816(&c[nj*4],      A0[0], A0[1], A0[2], A0[3], B0[nj], B1[nj]);
                            mma16816(&c[32 + nj*4], A1[0], A1[1], A1[2], A1[3], B0[nj], B1[nj]);
                        }
                    }
                }
            }

            // ---- epilogue: fragments -> g_convh (fp16) + stats in regs ----
            const int h_r = p + 4*k + 2*rsel;
            const int coB = 2*(L & 3);
            const int pxq = L >> 2;
            #pragma unroll
            for (int nj = 0; nj < 8; nj++) {
                const int co = nj*8 + coB;
                const size_t gb0 = (((size_t)(n*64 + co)) << 16) + (size_t)h_r*256 + w0;
                const size_t gb1 = gb0 + HW;   // co+1
                #pragma unroll
                for (int mi = 0; mi < 2; mi++) {
                    const float* cf = &c[mi*32 + nj*4];
                    const int px0 = Pm + mi*16 + pxq;
                    g_convh[gb0 + px0]     = __float2half_rn(cf[0]);
                    g_convh[gb1 + px0]     = __float2half_rn(cf[1]);
                    g_convh[gb0 + px0 + 8] = __float2half_rn(cf[2]);
                    g_convh[gb1 + px0 + 8] = __float2half_rn(cf[3]);
                    accS2[nj].x += cf[0] + cf[2];
                    accS2[nj].y += cf[1] + cf[3];
                    accQ2[nj].x += cf[0]*cf[0] + cf[2]*cf[2];
                    accQ2[nj].y += cf[1]*cf[1] + cf[3]*cf[3];
                }
            }
        }
    }

    // ---- stats reduction: butterfly over lanes sharing (L&3), then smem ----
    #pragma unroll
    for (int nj = 0; nj < 8; nj++) {
        #pragma unroll
        for (int off = 4; off < 32; off <<= 1) {
            accS2[nj].x += __shfl_xor_sync(0xffffffffu, accS2[nj].x, off);
            accS2[nj].y += __shfl_xor_sync(0xffffffffu, accS2[nj].y, off);
            accQ2[nj].x += __shfl_xor_sync(0xffffffffu, accQ2[nj].x, off);
            accQ2[nj].y += __shfl_xor_sync(0xffffffffu, accQ2[nj].y, off);
        }
    }
    if (L < 4) {
        #pragma unroll
        for (int nj = 0; nj < 8; nj++) {
            const int co = nj*8 + 2*L;
            sredS[wi*64 + co]     = accS2[nj].x;
            sredS[wi*64 + co + 1] = accS2[nj].y;
            sredQ[wi*64 + co]     = accQ2[nj].x;
            sredQ[wi*64 + co + 1] = accQ2[nj].y;
        }
    }
    __syncthreads();
    if (t < 64) {
        float s = 0.f, q = 0.f;
        #pragma unroll
        for (int w = 0; w < 8; w++) { s += sredS[w*64 + t]; q += sredQ[w*64 + t]; }
        g_psum[t*148 + blockIdx.x] = s;
        g_psq [t*148 + blockIdx.x] = q;
    }
}

// ---------------------------------------------------------------------------
__global__ void finalize_stats(const float* __restrict__ gamma,
                               const float* __restrict__ beta)
{
    int c = threadIdx.x;   // 64 threads
    float s = 0.f, q = 0.f;
    for (int b = 0; b < 148; b++) { s += g_psum[c*148 + b]; q += g_psq[c*148 + b]; }
    const float invM = 1.f / (float)M_PER_CH;
    float m   = s * invM;
    float var = q * invM - m*m;
    float inv = rsqrtf(var + 1e-5f);
    float sc  = gamma[c] * inv;
    g_scale[c] = sc;
    g_shift[c] = beta[c] - sc * m;
}

// ---------------------------------------------------------------------------
// normalize + ReLU + 4x4 block bitonic sort; write [a | y]  (DRAM roofline)
// ---------------------------------------------------------------------------
__global__ __launch_bounds__(256) void bn_sort_kernel(float* __restrict__ out)
{
    int tid = blockIdx.x * 256 + threadIdx.x;
    int bw = tid & 63, bh = (tid >> 6) & 63, c = (tid >> 12) & 63, n = tid >> 18;
    float sc = g_scale[c], sh = g_shift[c];

    size_t ibase = ((((size_t)(n*64 + c)) << 8) + bh*4) * 256 + bw*4;
    float v[16];
    #pragma unroll
    for (int r = 0; r < 4; r++) {
        uint2 raw = *(const uint2*)&g_convh[ibase + (size_t)r*256];
        float2 f01 = __half22float2(*(__half2*)&raw.x);
        float2 f23 = __half22float2(*(__half2*)&raw.y);
        v[r*4+0] = fmaxf(fmaf(f01.x, sc, sh), 0.f);
        v[r*4+1] = fmaxf(fmaf(f01.y, sc, sh), 0.f);
        v[r*4+2] = fmaxf(fmaf(f23.x, sc, sh), 0.f);
        v[r*4+3] = fmaxf(fmaf(f23.y, sc, sh), 0.f);
    }
    size_t obase = ((((size_t)(n*128 + c)) << 8) + bh*4) * 256 + bw*4;
    #pragma unroll
    for (int r = 0; r < 4; r++)
        *(float4*)&out[obase + (size_t)r*256] =
            make_float4(v[r*4+0], v[r*4+1], v[r*4+2], v[r*4+3]);

    #pragma unroll
    for (int k = 2; k <= 16; k <<= 1)
        #pragma unroll
        for (int j = k >> 1; j > 0; j >>= 1)
            #pragma unroll
            for (int i = 0; i < 16; i++) {
                int ix = i ^ j;
                if (ix > i) {
                    float a = v[i], b = v[ix];
                    float lo = fminf(a, b), hi = fmaxf(a, b);
                    bool up = ((i & k) == 0);
                    v[i] = up ? lo : hi; v[ix] = up ? hi : lo;
                }
            }

    size_t ybase = obase + ((size_t)64 << 16);
    #pragma unroll
    for (int r = 0; r < 4; r++)
        *(float4*)&out[ybase + (size_t)r*256] =
            make_float4(v[r*4+0], v[r*4+1], v[r*4+2], v[r*4+3]);
}

// ---------------------------------------------------------------------------
extern "C" void kernel_launch(void* const* d_in, const int* in_sizes, int n_in,
                              void* d_out, int out_size)
{
    const float* x     = (const float*)d_in[0];
    const float* wgt   = (const float*)d_in[1];
    // d_in[2] = conv_b : cancels exactly in training-mode BN
    const float* gamma = (const float*)d_in[3];
    const float* beta  = (const float*)d_in[4];
    float* out = (float*)d_out;

    cudaFuncSetAttribute(conv_tc, cudaFuncAttributeMaxDynamicSharedMemorySize, SMEM_REQ);
    conv_tc<<<148, 256, SMEM_REQ>>>(x, wgt);
    finalize_stats<<<1, 64>>>(gamma, beta);
    bn_sort_kernel<<<16384, 256>>>(out);
}

// round 13
// speedup vs baseline: 1.0901x; 1.0901x over previous
#include <cuda_runtime.h>
#include <cuda_fp16.h>
#include <cstdint>

#define HW 65536
#define M_PER_CH (16*HW)

__device__ __half g_convh[(size_t)16*64*HW];   // 128 MB fp16 scratch
__device__ float g_psum[64*148];
__device__ float g_psq[64*148];
__device__ float g_scale[64];
__device__ float g_shift[64];

// SMEM layout (dynamic):
//   W tiles : [0, 82944)            9 taps x [64 co][72 halves] (stride 144B)
//   A ring  : [82944, +4*19008)     4 slots x [132 px][72 halves]
#define WOFF 0
#define AOFF 82944
#define ATILE 19008
#define SMEM_REQ (82944 + 4*19008)
#define WTAP 9216      // 64*144

__device__ __forceinline__ uint32_t s2u(const void* p) {
    uint32_t a;
    asm("{ .reg .u64 t; cvta.to.shared.u64 t, %1; cvt.u32.u64 %0, t; }" : "=r"(a) : "l"(p));
    return a;
}
__device__ __forceinline__ void ldsm4(uint32_t& r0, uint32_t& r1, uint32_t& r2, uint32_t& r3,
                                      uint32_t addr) {
    asm volatile("ldmatrix.sync.aligned.m8n8.x4.shared.b16 {%0,%1,%2,%3}, [%4];"
                 : "=r"(r0), "=r"(r1), "=r"(r2), "=r"(r3) : "r"(addr));
}
__device__ __forceinline__ void mma16816(float* c, uint32_t a0, uint32_t a1, uint32_t a2,
                                         uint32_t a3, uint32_t b0, uint32_t b1) {
    asm volatile("mma.sync.aligned.m16n8k16.row.col.f32.f16.f16.f32 "
                 "{%0,%1,%2,%3}, {%4,%5,%6,%7}, {%8,%9}, {%0,%1,%2,%3};"
                 : "+f"(c[0]), "+f"(c[1]), "+f"(c[2]), "+f"(c[3])
                 : "r"(a0), "r"(a1), "r"(a2), "r"(a3), "r"(b0), "r"(b1));
}
__device__ __forceinline__ uint32_t packh2(float a, float b) {
    __half2 h = __floats2half2_rn(a, b);
    return *(uint32_t*)&h;
}

// Load one x row (132 px x 64 ci) into regs; tg in [0,256)
__device__ __forceinline__ void stage_load(const float* __restrict__ x, int n, int hrow,
                                           int w0, int tg, uint4 pk[4], uint4& pke)
{
    const bool rowok = ((unsigned)hrow < 256u);
    const int px   = tg & 127;
    const int octh = tg >> 7;
    const int wg   = w0 - 2 + px;
    const bool wok = rowok && ((unsigned)wg < 256u);
    const size_t rb = (size_t)(hrow*256 + wg);

    #pragma unroll
    for (int r = 0; r < 4; r++) {
        const int oct = 2*r + octh;
        const size_t base = (((size_t)(n*64 + oct*8)) << 16) + rb;
        float v[8];
        #pragma unroll
        for (int i = 0; i < 8; i++)
            v[i] = wok ? __ldg(&x[base + ((size_t)i << 16)]) : 0.f;
        pk[r].x = packh2(v[0], v[1]);
        pk[r].y = packh2(v[2], v[3]);
        pk[r].z = packh2(v[4], v[5]);
        pk[r].w = packh2(v[6], v[7]);
    }
    pke = make_uint4(0, 0, 0, 0);
    if (tg < 32) {
        const int pxe = 128 + (tg & 3);
        const int oct = tg >> 2;
        const int we = w0 - 2 + pxe;
        const bool ewok = rowok && ((unsigned)we < 256u);
        const size_t base = (((size_t)(n*64 + oct*8)) << 16) + (size_t)(hrow*256 + we);
        float v[8];
        #pragma unroll
        for (int i = 0; i < 8; i++)
            v[i] = ewok ? __ldg(&x[base + ((size_t)i << 16)]) : 0.f;
        pke.x = packh2(v[0], v[1]);
        pke.y = packh2(v[2], v[3]);
        pke.z = packh2(v[4], v[5]);
        pke.w = packh2(v[6], v[7]);
    }
}

__device__ __forceinline__ void stage_store(char* sm, int slot, int tg,
                                            const uint4 pk[4], const uint4& pke)
{
    char* base = sm + AOFF + slot * ATILE;
    const int px = tg & 127, octh = tg >> 7;
    #pragma unroll
    for (int r = 0; r < 4; r++)
        *(uint4*)(base + px*144 + (2*r + octh)*16) = pk[r];
    if (tg < 32)
        *(uint4*)(base + (128 + (tg & 3))*144 + (tg >> 2)*16) = pke;
}

// ---------------------------------------------------------------------------
// HMMA implicit-GEMM dilated conv + fused channel stats.
// 512 threads / 16 warps: double-row iterations; warp = (row, M-pos, N-half),
// each warp M=32 x N=32 (c[32], low reg pressure). 4-slot A ring,
// two staging groups of 256 threads each stage one row per iteration.
// Output stored fp16 to g_convh; stats kept fp32 in registers.
// ---------------------------------------------------------------------------
__global__ __launch_bounds__(512, 1)
void conv_tc(const float* __restrict__ x, const float* __restrict__ wgt)
{
    extern __shared__ char sm[];
    __shared__ float sredS[16*64], sredQ[16*64];

    const int t  = threadIdx.x;
    const int L  = t & 31;
    const int wi = t >> 5;
    const int rsel = wi >> 3;            // 0: row h, 1: row h+2
    const int Pm   = ((wi >> 1) & 3) * 32;
    const int Nb   = (wi & 1) * 32;
    const int g    = t >> 8;             // staging group 0/1
    const int tg   = t & 255;

    // zero stats scratch (each warp only writes its 32-co half later)
    sredS[t] = 0.f; sredS[512 + t] = 0.f;
    sredQ[t] = 0.f; sredQ[512 + t] = 0.f;

    // ---- stage weights: [tap][co][ci] fp16, row stride 144B ----
    {
        const int co  = t & 63;
        const int oct = t >> 6;   // 0..7
        for (int tap = 0; tap < 9; tap++) {
            float v[8];
            #pragma unroll
            for (int i = 0; i < 8; i++)
                v[i] = __ldg(&wgt[co*576 + (oct*8 + i)*9 + tap]);
            uint4 p;
            p.x = packh2(v[0], v[1]); p.y = packh2(v[2], v[3]);
            p.z = packh2(v[4], v[5]); p.w = packh2(v[6], v[7]);
            *(uint4*)(sm + WOFF + tap*WTAP + co*144 + oct*16) = p;
        }
    }

    const uint32_t Ab = s2u(sm + AOFF);
    const uint32_t Wb = s2u(sm + WOFF);

    uint32_t aoffm[2];
    #pragma unroll
    for (int mi = 0; mi < 2; mi++)
        aoffm[mi] = (uint32_t)((Pm + mi*16 + (L & 15)) * 144 + ((L >> 4) * 16));
    const uint32_t bconst = Wb + (uint32_t)((Nb + ((L >> 3) & 3)*8 + (L & 7)) * 144);

    float2 accS2[4], accQ2[4];
    #pragma unroll
    for (int i = 0; i < 4; i++) {
        accS2[i] = make_float2(0.f, 0.f);
        accQ2[i] = make_float2(0.f, 0.f);
    }

    // double-tile partition: 4096 units over 148 CTAs; chain = 64 units
    const int d0 = (blockIdx.x * 4096) / 148;
    const int d1 = ((blockIdx.x + 1) * 4096) / 148;

    uint4 pk[4], pke;
    int D = d0;

    __syncthreads();   // weights staged, sred zeroed

    while (D < d1) {
        const int chain = D >> 6;
        int k = D & 63;
        const int n  = chain >> 2;
        const int wc = (chain >> 1) & 1;
        const int p  = chain & 1;
        const int w0 = wc << 7;
        const int seg_end = (((chain + 1) << 6) < d1) ? ((chain + 1) << 6) : d1;

        // prologue (group g): store row j=2k+g (x row p+2(2k+g)-2) into slot,
        // then prefetch j=2k+2+g into pk.
        stage_load(x, n, p + 2*(2*k + g) - 2, w0, tg, pk, pke);
        stage_store(sm, (2*k + g) & 3, tg, pk, pke);
        stage_load(x, n, p + 2*(2*k + 2 + g) - 2, w0, tg, pk, pke);

        for (; D < seg_end; D++, k++) {
            stage_store(sm, (2*k + 2 + g) & 3, tg, pk, pke);
            __syncthreads();

            // prefetch next row for this group (hidden under the MMA loop)
            if (D + 1 < seg_end)
                stage_load(x, n, p + 2*(2*k + 4 + g) - 2, w0, tg, pk, pke);

            float c[32];
            #pragma unroll
            for (int i = 0; i < 32; i++) c[i] = 0.f;

            #pragma unroll
            for (int kh = 0; kh < 3; kh++) {
                const int sl = (2*k + rsel + kh) & 3;
                const uint32_t abase = Ab + (uint32_t)sl * ATILE;
                #pragma unroll
                for (int kw = 0; kw < 3; kw++) {
                    const uint32_t boffb = (uint32_t)((kh*3 + kw)*WTAP);
                    #pragma unroll
                    for (int ks = 0; ks < 4; ks++) {
                        const uint32_t aoff = (uint32_t)(kw*288 + ks*32);
                        const uint32_t boff = boffb + (uint32_t)(ks*32);
                        uint32_t A0[4], A1[4], B0[4], B1[4];
                        ldsm4(A0[0], A0[1], A0[2], A0[3], abase + aoffm[0] + aoff);
                        ldsm4(A1[0], A1[1], A1[2], A1[3], abase + aoffm[1] + aoff);
                        ldsm4(B0[0], B0[1], B0[2], B0[3], bconst + boff);
                        ldsm4(B1[0], B1[1], B1[2], B1[3], bconst + boff + 16);
                        #pragma unroll
                        for (int nj = 0; nj < 4; nj++) {
                            mma16816(&c[nj*4],      A0[0], A0[1], A0[2], A0[3], B0[nj], B1[nj]);
                            mma16816(&c[16 + nj*4], A1[0], A1[1], A1[2], A1[3], B0[nj], B1[nj]);
                        }
                    }
                }
            }
            __syncthreads();   // ldsm reads complete before slots are overwritten

            // ---- epilogue: fragments -> g_convh (fp16, m16n8 C layout) ----
            const int h_r = p + 4*k + 2*rsel;
            const int coB = 2*(L & 3);
            const int pxq = L >> 2;
            #pragma unroll
            for (int nj = 0; nj < 4; nj++) {
                const int co = Nb + nj*8 + coB;
                const size_t gb0 = (((size_t)(n*64 + co)) << 16) + (size_t)h_r*256 + w0;
                const size_t gb1 = gb0 + HW;   // co+1
                #pragma unroll
                for (int mi = 0; mi < 2; mi++) {
                    const float* cf = &c[mi*16 + nj*4];
                    const int px0 = Pm + mi*16 + pxq;
                    g_convh[gb0 + px0]     = __float2half_rn(cf[0]);
                    g_convh[gb1 + px0]     = __float2half_rn(cf[1]);
                    g_convh[gb0 + px0 + 8] = __float2half_rn(cf[2]);
                    g_convh[gb1 + px0 + 8] = __float2half_rn(cf[3]);
                    accS2[nj].x += cf[0] + cf[2];
                    accS2[nj].y += cf[1] + cf[3];
                    accQ2[nj].x += cf[0]*cf[0] + cf[2]*cf[2];
                    accQ2[nj].y += cf[1]*cf[1] + cf[3]*cf[3];
                }
            }
        }
    }

    // ---- stats: butterfly over lanes sharing (L&3), write own co half ----
    #pragma unroll
    for (int nj = 0; nj < 4; nj++) {
        #pragma unroll
        for (int off = 4; off < 32; off <<= 1) {
            accS2[nj].x += __shfl_xor_sync(0xffffffffu, accS2[nj].x, off);
            accS2[nj].y += __shfl_xor_sync(0xffffffffu, accS2[nj].y, off);
            accQ2[nj].x += __shfl_xor_sync(0xffffffffu, accQ2[nj].x, off);
            accQ2[nj].y += __shfl_xor_sync(0xffffffffu, accQ2[nj].y, off);
        }
    }
    if (L < 4) {
        #pragma unroll
        for (int nj = 0; nj < 4; nj++) {
            const int co = Nb + nj*8 + 2*L;
            sredS[wi*64 + co]     = accS2[nj].x;
            sredS[wi*64 + co + 1] = accS2[nj].y;
            sredQ[wi*64 + co]     = accQ2[nj].x;
            sredQ[wi*64 + co + 1] = accQ2[nj].y;
        }
    }
    __syncthreads();
    if (t < 64) {
        float s = 0.f, q = 0.f;
        #pragma unroll
        for (int w = 0; w < 16; w++) { s += sredS[w*64 + t]; q += sredQ[w*64 + t]; }
        g_psum[t*148 + blockIdx.x] = s;
        g_psq [t*148 + blockIdx.x] = q;
    }
}

// ---------------------------------------------------------------------------
__global__ void finalize_stats(const float* __restrict__ gamma,
                               const float* __restrict__ beta)
{
    int c = threadIdx.x;   // 64 threads
    float s = 0.f, q = 0.f;
    for (int b = 0; b < 148; b++) { s += g_psum[c*148 + b]; q += g_psq[c*148 + b]; }
    const float invM = 1.f / (float)M_PER_CH;
    float m   = s * invM;
    float var = q * invM - m*m;
    float inv = rsqrtf(var + 1e-5f);
    float sc  = gamma[c] * inv;
    g_scale[c] = sc;
    g_shift[c] = beta[c] - sc * m;
}

// ---------------------------------------------------------------------------
// normalize + ReLU + 4x4 block bitonic sort; write [a | y]  (DRAM roofline)
// ---------------------------------------------------------------------------
__global__ __launch_bounds__(256) void bn_sort_kernel(float* __restrict__ out)
{
    int tid = blockIdx.x * 256 + threadIdx.x;
    int bw = tid & 63, bh = (tid >> 6) & 63, c = (tid >> 12) & 63, n = tid >> 18;
    float sc = g_scale[c], sh = g_shift[c];

    size_t ibase = ((((size_t)(n*64 + c)) << 8) + bh*4) * 256 + bw*4;
    float v[16];
    #pragma unroll
    for (int r = 0; r < 4; r++) {
        uint2 raw = *(const uint2*)&g_convh[ibase + (size_t)r*256];
        float2 f01 = __half22float2(*(__half2*)&raw.x);
        float2 f23 = __half22float2(*(__half2*)&raw.y);
        v[r*4+0] = fmaxf(fmaf(f01.x, sc, sh), 0.f);
        v[r*4+1] = fmaxf(fmaf(f01.y, sc, sh), 0.f);
        v[r*4+2] = fmaxf(fmaf(f23.x, sc, sh), 0.f);
        v[r*4+3] = fmaxf(fmaf(f23.y, sc, sh), 0.f);
    }
    size_t obase = ((((size_t)(n*128 + c)) << 8) + bh*4) * 256 + bw*4;
    #pragma unroll
    for (int r = 0; r < 4; r++)
        *(float4*)&out[obase + (size_t)r*256] =
            make_float4(v[r*4+0], v[r*4+1], v[r*4+2], v[r*4+3]);

    #pragma unroll
    for (int k = 2; k <= 16; k <<= 1)
        #pragma unroll
        for (int j = k >> 1; j > 0; j >>= 1)
            #pragma unroll
            for (int i = 0; i < 16; i++) {
                int ix = i ^ j;
                if (ix > i) {
                    float a = v[i], b = v[ix];
                    float lo = fminf(a, b), hi = fmaxf(a, b);
                    bool up = ((i & k) == 0);
                    v[i] = up ? lo : hi; v[ix] = up ? hi : lo;
                }
            }

    size_t ybase = obase + ((size_t)64 << 16);
    #pragma unroll
    for (int r = 0; r < 4; r++)
        *(float4*)&out[ybase + (size_t)r*256] =
            make_float4(v[r*4+0], v[r*4+1], v[r*4+2], v[r*4+3]);
}

// ---------------------------------------------------------------------------
extern "C" void kernel_launch(void* const* d_in, const int* in_sizes, int n_in,
                              void* d_out, int out_size)
{
    const float* x     = (const float*)d_in[0];
    const float* wgt   = (const float*)d_in[1];
    // d_in[2] = conv_b : cancels exactly in training-mode BN
    const float* gamma = (const float*)d_in[3];
    const float* beta  = (const float*)d_in[4];
    float* out = (float*)d_out;

    cudaFuncSetAttribute(conv_tc, cudaFuncAttributeMaxDynamicSharedMemorySize, SMEM_REQ);
    conv_tc<<<148, 512, SMEM_REQ>>>(x, wgt);
    finalize_stats<<<1, 64>>>(gamma, beta);
    bn_sort_kernel<<<16384, 256>>>(out);
}